// round 16
// baseline (speedup 1.0000x reference)
#include <cuda_runtime.h>
#include <cuda_fp16.h>

#define W_ 768
#define H_ 768
#define N_ 16
#define HW_ (H_ * W_)
#define BX 32
#define BY 16
#define NT (BX * BY)           /* 512 */
#define RPB 64                 /* pixel rows per block (4 per thread) */
#define RX_ 8                  /* x halo: left 8 (alignment), right 8 */
#define RY_ 7                  /* y halo: 7 suffices for |f| < 6.98 */
#define TW 48                  /* tile width (mult of 4) */
#define TH (RPB + 2 * RY_)     /* 78 */
#define TSZ (TW * TH)          /* 3744 half2 cells */
#define NV4 (TSZ / 4)          /* 936 */
#define GX_ (W_ / BX)          /* 24 */
#define GY_ (H_ / RPB)         /* 12 */
#define NBLK (GX_ * GY_ * N_)  /* 4608 */
#define EPS2 1.0e-6f
#define INVW (1.0f / 767.0f)
#define INVH (1.0f / 767.0f)
#define WM1F 767.0f
#define HM1F 767.0f
#define CLEAN_TH_H 6.95f
#define CLEAN_TH_F 6.98f

__device__ float g_partials[NBLK];
__device__ unsigned long long g_ticket;  // monotonic across graph replays

typedef unsigned long long u64;

__device__ __forceinline__ u64 packf2(float lo, float hi)
{
    u64 r; asm("mov.b64 %0, {%1, %2};" : "=l"(r) : "f"(lo), "f"(hi)); return r;
}
__device__ __forceinline__ void unpackf2(u64 v, float& lo, float& hi)
{
    asm("mov.b64 {%0, %1}, %2;" : "=f"(lo), "=f"(hi) : "l"(v));
}
#define ADD_F32X2(out, a, b) \
    asm("add.rn.f32x2 %0, %1, %2;" : "=l"(out) : "l"(a), "l"(b))
#define MUL_F32X2(out, a, b) \
    asm("mul.rn.f32x2 %0, %1, %2;" : "=l"(out) : "l"(a), "l"(b))

__device__ __forceinline__ float fast_sqrt(float v)
{
    return v * __frsqrt_rn(v);   // v >= EPS2 > 0 always
}
__device__ __forceinline__ unsigned h2u(__half2 h)
{
    return *reinterpret_cast<unsigned*>(&h);
}
__device__ __forceinline__ __half2 u2h(unsigned u)
{
    return *reinterpret_cast<__half2*>(&u);
}

// General m1 = warp(GridXY, flo1) at integer pixel (ix,iy): closed form.
__device__ __forceinline__ float2 m1_from(float fxv, float fyv, int ix, int iy)
{
    float gx = (float)ix + fxv;
    float gy = (float)iy + fyv;
    float x0f = floorf(gx), y0f = floorf(gy);
    float wx1 = gx - x0f, wy1 = gy - y0f;
    float wx0 = 1.0f - wx1, wy0 = 1.0f - wy1;
    int x0 = (int)x0f, y0 = (int)y0f;
    bool vx0 = ((unsigned)x0 < (unsigned)W_);
    bool vx1 = ((unsigned)(x0 + 1) < (unsigned)W_);
    bool vy0 = ((unsigned)y0 < (unsigned)H_);
    bool vy1 = ((unsigned)(y0 + 1) < (unsigned)H_);
    float c00 = (vx0 && vy0) ? wx0 * wy0 : 0.0f;
    float c10 = (vx1 && vy0) ? wx1 * wy0 : 0.0f;
    float c01 = (vx0 && vy1) ? wx0 * wy1 : 0.0f;
    float c11 = (vx1 && vy1) ? wx1 * wy1 : 0.0f;
    float m = (c00 + c10) + (c01 + c11);
    float cx1 = c10 + c11;
    float cy1 = c01 + c11;
    float ox = fmaf(m, (float)x0, cx1) * INVW;
    float oy = fmaf(m, (float)y0, cy1) * INVH;
    float M = (m < 0.9999f) ? 0.0f : 1.0f;
    return make_float2(ox * M, oy * M);
}

__device__ __forceinline__ float slow_eval(
    float2 f00, float2 f10, float2 f01, float2 f11,
    int x0, int y0, float wx0, float wx1, float wy0, float wy1,
    float Gx, float Gy)
{
    int x1 = x0 + 1, y1 = y0 + 1;
    bool vx0 = ((unsigned)x0 < (unsigned)W_);
    bool vx1 = ((unsigned)x1 < (unsigned)W_);
    bool vy0 = ((unsigned)y0 < (unsigned)H_);
    bool vy1 = ((unsigned)y1 < (unsigned)H_);
    float w00 = (vx0 && vy0) ? wx0 * wy0 : 0.0f;
    float w10 = (vx1 && vy0) ? wx1 * wy0 : 0.0f;
    float w01 = (vx0 && vy1) ? wx0 * wy1 : 0.0f;
    float w11 = (vx1 && vy1) ? wx1 * wy1 : 0.0f;

    float2 v00 = m1_from(f00.x, f00.y, x0, y0);
    float2 v10 = m1_from(f10.x, f10.y, x1, y0);
    float2 v01 = m1_from(f01.x, f01.y, x0, y1);
    float2 v11 = m1_from(f11.x, f11.y, x1, y1);

    float mask = (w00 + w10) + (w01 + w11);
    float mx = fmaf(w00, v00.x, fmaf(w10, v10.x, fmaf(w01, v01.x, w11 * v11.x)));
    float my = fmaf(w00, v00.y, fmaf(w10, v10.y, fmaf(w01, v01.y, w11 * v11.y)));
    float M = (mask < 0.9999f) ? 0.0f : 1.0f;
    mx *= M; my *= M;
    float dx = Gx - mx, dy = Gy - my;
    return fast_sqrt(fmaf(dx, dx, fmaf(dy, dy, EPS2)));
}

// General per-pixel path (margin/dirty pixels).
__device__ __forceinline__ float dir_diff(const __half2* __restrict__ t1,
                                          const float* __restrict__ g1x,
                                          const float* __restrict__ g1y,
                                          float f2x, float f2y,
                                          int px, int py, int tx0, int ty0,
                                          float Gx, float Gy)
{
    float sxf = (float)px + f2x;
    float syf = (float)py + f2y;
    float x0f = floorf(sxf), y0f = floorf(syf);
    float wx1 = sxf - x0f, wy1 = syf - y0f;
    float wx0 = 1.0f - wx1, wy0 = 1.0f - wy1;
    int x0 = (int)x0f, y0 = (int)y0f;

    int lx0 = x0 - tx0, ly0 = y0 - ty0;
    if (((unsigned)lx0 <= (unsigned)(TW - 2)) &
        ((unsigned)ly0 <= (unsigned)(TH - 2))) {
        int b = ly0 * TW + lx0;
        float2 f00 = __half22float2(t1[b]);
        float2 f10 = __half22float2(t1[b + 1]);
        float2 f01 = __half22float2(t1[b + TW]);
        float2 f11 = __half22float2(t1[b + TW + 1]);

        float x1f = x0f + 1.0f, y1f = y0f + 1.0f;
        float mnfx = fminf(fminf(f00.x, f01.x), fminf(f10.x, f11.x));
        float mxfx = fmaxf(fmaxf(f00.x, f01.x), fmaxf(f10.x, f11.x));
        float mnfy = fminf(fminf(f00.y, f01.y), fminf(f10.y, f11.y));
        float mxfy = fmaxf(fmaxf(f00.y, f01.y), fmaxf(f10.y, f11.y));
        bool inner = (sxf >= 0.0f) & (sxf <= WM1F) &
                     (syf >= 0.0f) & (syf <= HM1F) &
                     (x0f + mnfx >= 0.0f) & (x1f + mxfx <= WM1F) &
                     (y0f + mnfy >= 0.0f) & (y1f + mxfy <= HM1F);
        if (inner) {
            float ftx = fmaf(wx1, f10.x - f00.x, f00.x);
            float fbx = fmaf(wx1, f11.x - f01.x, f01.x);
            float bfx = fmaf(wy1, fbx - ftx, ftx);
            float fty = fmaf(wx1, f10.y - f00.y, f00.y);
            float fby = fmaf(wx1, f11.y - f01.y, f01.y);
            float bfy = fmaf(wy1, fby - fty, fty);
            float dx = (f2x + bfx) * INVW;
            float dy = (f2y + bfy) * INVH;
            return fast_sqrt(fmaf(dx, dx, fmaf(dy, dy, EPS2)));
        }
        return slow_eval(f00, f10, f01, f11, x0, y0, wx0, wx1, wy0, wy1, Gx, Gy);
    }
    {
        int x1 = x0 + 1, y1 = y0 + 1;
        int xc0 = min(max(x0, 0), W_ - 1);
        int xc1 = min(max(x1, 0), W_ - 1);
        int yc0 = min(max(y0, 0), H_ - 1);
        int yc1 = min(max(y1, 0), H_ - 1);
        int b00 = yc0 * W_ + xc0, b10 = yc0 * W_ + xc1;
        int b01 = yc1 * W_ + xc0, b11 = yc1 * W_ + xc1;
        float2 f00 = make_float2(__ldg(g1x + b00), __ldg(g1y + b00));
        float2 f10 = make_float2(__ldg(g1x + b10), __ldg(g1y + b10));
        float2 f01 = make_float2(__ldg(g1x + b01), __ldg(g1y + b01));
        float2 f11 = make_float2(__ldg(g1x + b11), __ldg(g1y + b11));
        return slow_eval(f00, f10, f01, f11, x0, y0, wx0, wx1, wy0, wy1, Gx, Gy);
    }
}

// Fast path: tile-relative coords (u,v > 0), packed f32x2 head/tail,
// lerp-form half2 bilerp.
__device__ __forceinline__ float dir_fast_u(const __half2* __restrict__ t1,
                                            u64 f2p, u64 uvb, u64 invp)
{
    u64 uvp; ADD_F32X2(uvp, uvb, f2p);
    float u, v; unpackf2(uvp, u, v);
    int iu = (int)u;                     // u,v > 0: trunc == floor
    int iv = (int)v;
    float wx1 = u - (float)iu;
    float wy1 = v - (float)iv;
    int b = iv * TW + iu;

    __half2 f00 = t1[b];
    __half2 f10 = t1[b + 1];
    __half2 f01 = t1[b + TW];
    __half2 f11 = t1[b + TW + 1];

    __half2 hx1 = __float2half2_rn(wx1);
    __half2 hy1 = __float2half2_rn(wy1);

    __half2 top = __hfma2(__hsub2(f10, f00), hx1, f00);
    __half2 bot = __hfma2(__hsub2(f11, f01), hx1, f01);
    __half2 r   = __hfma2(__hsub2(bot, top), hy1, top);
    float2 bf = __half22float2(r);

    u64 dp; ADD_F32X2(dp, f2p, packf2(bf.x, bf.y));
    MUL_F32X2(dp, dp, invp);
    float dx, dy; unpackf2(dp, dx, dy);
    return fast_sqrt(fmaf(dx, dx, fmaf(dy, dy, EPS2)));
}

__global__ __launch_bounds__(NT, 4)
void fused_cycle_kernel(const float* __restrict__ A, const float* __restrict__ B,
                        float* __restrict__ out)
{
    __shared__ __half2 tA[TSZ];
    __shared__ __half2 tB[TSZ];

    int n = blockIdx.z;
    const float* Ax = A + (size_t)n * 2 * HW_;
    const float* Ay = Ax + HW_;
    const float* Bx = B + (size_t)n * 2 * HW_;
    const float* By = Bx + HW_;

    int tx0 = blockIdx.x * BX - RX_;    // % 4 == 0 for interior bx
    int ty0 = blockIdx.y * RPB - RY_;
    int tid = threadIdx.y * BX + threadIdx.x;

    int dirty = 0;

    // Tile fill: tile cell == clamped-global value, quantized to half2.
    if (blockIdx.x >= 1 && blockIdx.x <= GX_ - 2) {
        __half2 macc = __float2half2_rn(0.0f);
        for (int i = tid; i < NV4; i += NT) {
            int ly = i / (TW / 4);
            int lxg = (i - ly * (TW / 4)) * 4;
            int gy = min(max(ty0 + ly, 0), H_ - 1);
            int idx = gy * W_ + tx0 + lxg;
            float4 ax = *(const float4*)(Ax + idx);
            float4 ay = *(const float4*)(Ay + idx);
            float4 bx = *(const float4*)(Bx + idx);
            float4 by = *(const float4*)(By + idx);
            int c = ly * TW + lxg;
            uint4 va = make_uint4(h2u(__floats2half2_rn(ax.x, ay.x)),
                                  h2u(__floats2half2_rn(ax.y, ay.y)),
                                  h2u(__floats2half2_rn(ax.z, ay.z)),
                                  h2u(__floats2half2_rn(ax.w, ay.w)));
            uint4 vb = make_uint4(h2u(__floats2half2_rn(bx.x, by.x)),
                                  h2u(__floats2half2_rn(bx.y, by.y)),
                                  h2u(__floats2half2_rn(bx.z, by.z)),
                                  h2u(__floats2half2_rn(bx.w, by.w)));
            *(uint4*)&tA[c] = va;
            *(uint4*)&tB[c] = vb;
            __half2 m0 = __hmax2(__habs2(u2h(va.x)), __habs2(u2h(va.y)));
            __half2 m1 = __hmax2(__habs2(u2h(va.z)), __habs2(u2h(va.w)));
            __half2 m2 = __hmax2(__habs2(u2h(vb.x)), __habs2(u2h(vb.y)));
            __half2 m3 = __hmax2(__habs2(u2h(vb.z)), __habs2(u2h(vb.w)));
            macc = __hmax2(macc, __hmax2(__hmax2(m0, m1), __hmax2(m2, m3)));
        }
        float hm = fmaxf(__half2float(__low2half(macc)),
                         __half2float(__high2half(macc)));
        if (hm >= CLEAN_TH_H) dirty = 1;
    } else {
        for (int i = tid; i < TSZ; i += NT) {
            int ly = i / TW, lx = i - ly * TW;
            int gx = min(max(tx0 + lx, 0), W_ - 1);
            int gy = min(max(ty0 + ly, 0), H_ - 1);
            int idx = gy * W_ + gx;
            float fax = __ldg(Ax + idx), fay = __ldg(Ay + idx);
            float fbx = __ldg(Bx + idx), fby = __ldg(By + idx);
            if (fmaxf(fmaxf(fabsf(fax), fabsf(fay)),
                      fmaxf(fabsf(fbx), fabsf(fby))) >= CLEAN_TH_F) dirty = 1;
            tA[i] = __floats2half2_rn(fax, fay);
            tB[i] = __floats2half2_rn(fbx, fby);
        }
    }

    // Own-pixel flows from global at fp32 (coalesced, batched; replaces
    // 8 LDS + cvts and overlaps with the fill barrier below).
    int px = blockIdx.x * BX + threadIdx.x;
    int py0 = blockIdx.y * RPB + threadIdx.y;
    float aox[4], aoy[4], box[4], boy[4];
    {
        int idx = py0 * W_ + px;
        #pragma unroll
        for (int r = 0; r < 4; r++) {
            aox[r] = __ldg(Ax + idx); aoy[r] = __ldg(Ay + idx);
            box[r] = __ldg(Bx + idx); boy[r] = __ldg(By + idx);
            idx += BY * W_;
        }
    }

    bool dataClean = (__syncthreads_or(dirty) == 0);  // also the fill barrier

    bool blockInterior = (blockIdx.x >= 1) & (blockIdx.x <= GX_ - 2) &
                         (blockIdx.y >= 1) & (blockIdx.y <= GY_ - 2);

    float s = 0.0f;
    if (blockInterior & dataClean) {
        const u64 invp = packf2(INVW, INVH);
        float ub = (float)(threadIdx.x + RX_);
        float vb = (float)(threadIdx.y + RY_);
        #pragma unroll
        for (int r = 0; r < 4; r++) {
            u64 uvb = packf2(ub, vb);
            s += dir_fast_u(tA, packf2(box[r], boy[r]), uvb, invp)
               + dir_fast_u(tB, packf2(aox[r], aoy[r]), uvb, invp);
            vb += (float)BY;
        }
    } else {
        bool pxIn = ((unsigned)(px - 14) <= 737u);
        const u64 invp = packf2(INVW, INVH);
        float ub = (float)(px - tx0);
        #pragma unroll
        for (int r = 0; r < 4; r++) {
            int py = py0 + r * BY;
            bool fast = dataClean & pxIn & ((unsigned)(py - 14) <= 737u);
            if (fast) {
                u64 uvb = packf2(ub, (float)(py - ty0));
                s += dir_fast_u(tA, packf2(box[r], boy[r]), uvb, invp)
                   + dir_fast_u(tB, packf2(aox[r], aoy[r]), uvb, invp);
            } else {
                float Gx = (float)px * INVW;
                float Gy = (float)py * INVH;
                s += dir_diff(tA, Ax, Ay, box[r], boy[r], px, py, tx0, ty0, Gx, Gy)
                   + dir_diff(tB, Bx, By, aox[r], aoy[r], px, py, tx0, ty0, Gx, Gy);
            }
        }
    }

    // Block reduction (16 warps)
    #pragma unroll
    for (int o = 16; o > 0; o >>= 1)
        s += __shfl_down_sync(0xffffffffu, s, o);
    __shared__ float shred[NT / 32];
    if ((tid & 31) == 0) shred[tid >> 5] = s;
    __syncthreads();
    if (tid < 16) {
        float v = shred[tid];
        #pragma unroll
        for (int o = 8; o > 0; o >>= 1)
            v += __shfl_down_sync(0x0000ffffu, v, o);
        if (tid == 0) {
            int bid = blockIdx.x + GX_ * (blockIdx.y + GY_ * blockIdx.z);
            g_partials[bid] = v;
        }
    }

    // Last-block-standing fused final reduce (deterministic).
    __shared__ bool amLast;
    __threadfence();
    if (tid == 0) {
        unsigned long long old = atomicAdd(&g_ticket, 1ULL);
        amLast = ((old % (unsigned long long)NBLK) == (unsigned long long)(NBLK - 1));
    }
    __syncthreads();
    if (amLast) {
        const float4* p4 = (const float4*)g_partials;  // NBLK % 4 == 0
        const int n4 = NBLK / 4;                       // 1152
        double acc = 0.0;
        for (int i = tid; i < n4; i += NT) {
            float4 v = __ldcg(p4 + i);
            acc += (double)((v.x + v.y) + (v.z + v.w));
        }
        #pragma unroll
        for (int o = 16; o > 0; o >>= 1)
            acc += __shfl_down_sync(0xffffffffu, acc, o);
        __shared__ double shd[NT / 32];
        if ((tid & 31) == 0) shd[tid >> 5] = acc;
        __syncthreads();
        if (tid < 16) {
            double v = shd[tid];
            #pragma unroll
            for (int o = 8; o > 0; o >>= 1)
                v += __shfl_down_sync(0x0000ffffu, v, o);
            if (tid == 0)
                out[0] = (float)(v / ((double)N_ * (double)HW_));
        }
    }
}

extern "C" void kernel_launch(void* const* d_in, const int* in_sizes, int n_in,
                              void* d_out, int out_size)
{
    const float* A = (const float*)d_in[0];  // UV_AtoB
    const float* B = (const float*)d_in[1];  // UV_BtoA
    dim3 block(BX, BY);
    dim3 grid(GX_, GY_, N_);
    fused_cycle_kernel<<<grid, block>>>(A, B, (float*)d_out);
}

// round 17
// speedup vs baseline: 1.0568x; 1.0568x over previous
#include <cuda_runtime.h>
#include <cuda_fp16.h>

#define W_ 768
#define H_ 768
#define N_ 16
#define HW_ (H_ * W_)
#define BX 32
#define BY 16
#define NT (BX * BY)           /* 512 */
#define RPB 64                 /* pixel rows per block (4 per thread) */
#define RX_ 8                  /* x halo: left 8 (alignment), right 8 */
#define RY_ 7                  /* y halo: 7 suffices for |f| < 6.98 */
#define TW 48                  /* tile width (mult of 4) */
#define TH (RPB + 2 * RY_)     /* 78 */
#define TSZ (TW * TH)          /* 3744 half2 cells */
#define NV4 (TSZ / 4)          /* 936 */
#define GX_ (W_ / BX)          /* 24 */
#define GY_ (H_ / RPB)         /* 12 */
#define NBLK (GX_ * GY_ * N_)  /* 4608 */
#define EPS2 1.0e-6f
#define INVW (1.0f / 767.0f)
#define INVH (1.0f / 767.0f)
#define WM1F 767.0f
#define HM1F 767.0f
#define CLEAN_TH_H 6.95f
#define CLEAN_TH_F 6.98f

__device__ float g_partials[NBLK];
__device__ unsigned long long g_ticket;  // monotonic across graph replays

typedef unsigned long long u64;

__device__ __forceinline__ u64 packf2(float lo, float hi)
{
    u64 r; asm("mov.b64 %0, {%1, %2};" : "=l"(r) : "f"(lo), "f"(hi)); return r;
}
__device__ __forceinline__ void unpackf2(u64 v, float& lo, float& hi)
{
    asm("mov.b64 {%0, %1}, %2;" : "=f"(lo), "=f"(hi) : "l"(v));
}
#define ADD_F32X2(out, a, b) \
    asm("add.rn.f32x2 %0, %1, %2;" : "=l"(out) : "l"(a), "l"(b))
#define MUL_F32X2(out, a, b) \
    asm("mul.rn.f32x2 %0, %1, %2;" : "=l"(out) : "l"(a), "l"(b))

__device__ __forceinline__ float fast_sqrt(float v)
{
    return v * __frsqrt_rn(v);   // v >= EPS2 > 0 always
}
__device__ __forceinline__ unsigned h2u(__half2 h)
{
    return *reinterpret_cast<unsigned*>(&h);
}
__device__ __forceinline__ __half2 u2h(unsigned u)
{
    return *reinterpret_cast<__half2*>(&u);
}

// General m1 = warp(GridXY, flo1) at integer pixel (ix,iy): closed form.
__device__ __forceinline__ float2 m1_from(float fxv, float fyv, int ix, int iy)
{
    float gx = (float)ix + fxv;
    float gy = (float)iy + fyv;
    float x0f = floorf(gx), y0f = floorf(gy);
    float wx1 = gx - x0f, wy1 = gy - y0f;
    float wx0 = 1.0f - wx1, wy0 = 1.0f - wy1;
    int x0 = (int)x0f, y0 = (int)y0f;
    bool vx0 = ((unsigned)x0 < (unsigned)W_);
    bool vx1 = ((unsigned)(x0 + 1) < (unsigned)W_);
    bool vy0 = ((unsigned)y0 < (unsigned)H_);
    bool vy1 = ((unsigned)(y0 + 1) < (unsigned)H_);
    float c00 = (vx0 && vy0) ? wx0 * wy0 : 0.0f;
    float c10 = (vx1 && vy0) ? wx1 * wy0 : 0.0f;
    float c01 = (vx0 && vy1) ? wx0 * wy1 : 0.0f;
    float c11 = (vx1 && vy1) ? wx1 * wy1 : 0.0f;
    float m = (c00 + c10) + (c01 + c11);
    float cx1 = c10 + c11;
    float cy1 = c01 + c11;
    float ox = fmaf(m, (float)x0, cx1) * INVW;
    float oy = fmaf(m, (float)y0, cy1) * INVH;
    float M = (m < 0.9999f) ? 0.0f : 1.0f;
    return make_float2(ox * M, oy * M);
}

__device__ __forceinline__ float slow_eval(
    float2 f00, float2 f10, float2 f01, float2 f11,
    int x0, int y0, float wx0, float wx1, float wy0, float wy1,
    float Gx, float Gy)
{
    int x1 = x0 + 1, y1 = y0 + 1;
    bool vx0 = ((unsigned)x0 < (unsigned)W_);
    bool vx1 = ((unsigned)x1 < (unsigned)W_);
    bool vy0 = ((unsigned)y0 < (unsigned)H_);
    bool vy1 = ((unsigned)y1 < (unsigned)H_);
    float w00 = (vx0 && vy0) ? wx0 * wy0 : 0.0f;
    float w10 = (vx1 && vy0) ? wx1 * wy0 : 0.0f;
    float w01 = (vx0 && vy1) ? wx0 * wy1 : 0.0f;
    float w11 = (vx1 && vy1) ? wx1 * wy1 : 0.0f;

    float2 v00 = m1_from(f00.x, f00.y, x0, y0);
    float2 v10 = m1_from(f10.x, f10.y, x1, y0);
    float2 v01 = m1_from(f01.x, f01.y, x0, y1);
    float2 v11 = m1_from(f11.x, f11.y, x1, y1);

    float mask = (w00 + w10) + (w01 + w11);
    float mx = fmaf(w00, v00.x, fmaf(w10, v10.x, fmaf(w01, v01.x, w11 * v11.x)));
    float my = fmaf(w00, v00.y, fmaf(w10, v10.y, fmaf(w01, v01.y, w11 * v11.y)));
    float M = (mask < 0.9999f) ? 0.0f : 1.0f;
    mx *= M; my *= M;
    float dx = Gx - mx, dy = Gy - my;
    return fast_sqrt(fmaf(dx, dx, fmaf(dy, dy, EPS2)));
}

// General per-pixel path (margin/dirty pixels).
__device__ __forceinline__ float dir_diff(const __half2* __restrict__ t1,
                                          const float* __restrict__ g1x,
                                          const float* __restrict__ g1y,
                                          float f2x, float f2y,
                                          int px, int py, int tx0, int ty0,
                                          float Gx, float Gy)
{
    float sxf = (float)px + f2x;
    float syf = (float)py + f2y;
    float x0f = floorf(sxf), y0f = floorf(syf);
    float wx1 = sxf - x0f, wy1 = syf - y0f;
    float wx0 = 1.0f - wx1, wy0 = 1.0f - wy1;
    int x0 = (int)x0f, y0 = (int)y0f;

    int lx0 = x0 - tx0, ly0 = y0 - ty0;
    if (((unsigned)lx0 <= (unsigned)(TW - 2)) &
        ((unsigned)ly0 <= (unsigned)(TH - 2))) {
        int b = ly0 * TW + lx0;
        float2 f00 = __half22float2(t1[b]);
        float2 f10 = __half22float2(t1[b + 1]);
        float2 f01 = __half22float2(t1[b + TW]);
        float2 f11 = __half22float2(t1[b + TW + 1]);

        float x1f = x0f + 1.0f, y1f = y0f + 1.0f;
        float mnfx = fminf(fminf(f00.x, f01.x), fminf(f10.x, f11.x));
        float mxfx = fmaxf(fmaxf(f00.x, f01.x), fmaxf(f10.x, f11.x));
        float mnfy = fminf(fminf(f00.y, f01.y), fminf(f10.y, f11.y));
        float mxfy = fmaxf(fmaxf(f00.y, f01.y), fmaxf(f10.y, f11.y));
        bool inner = (sxf >= 0.0f) & (sxf <= WM1F) &
                     (syf >= 0.0f) & (syf <= HM1F) &
                     (x0f + mnfx >= 0.0f) & (x1f + mxfx <= WM1F) &
                     (y0f + mnfy >= 0.0f) & (y1f + mxfy <= HM1F);
        if (inner) {
            float ftx = fmaf(wx1, f10.x - f00.x, f00.x);
            float fbx = fmaf(wx1, f11.x - f01.x, f01.x);
            float bfx = fmaf(wy1, fbx - ftx, ftx);
            float fty = fmaf(wx1, f10.y - f00.y, f00.y);
            float fby = fmaf(wx1, f11.y - f01.y, f01.y);
            float bfy = fmaf(wy1, fby - fty, fty);
            float dx = (f2x + bfx) * INVW;
            float dy = (f2y + bfy) * INVH;
            return fast_sqrt(fmaf(dx, dx, fmaf(dy, dy, EPS2)));
        }
        return slow_eval(f00, f10, f01, f11, x0, y0, wx0, wx1, wy0, wy1, Gx, Gy);
    }
    {
        int x1 = x0 + 1, y1 = y0 + 1;
        int xc0 = min(max(x0, 0), W_ - 1);
        int xc1 = min(max(x1, 0), W_ - 1);
        int yc0 = min(max(y0, 0), H_ - 1);
        int yc1 = min(max(y1, 0), H_ - 1);
        int b00 = yc0 * W_ + xc0, b10 = yc0 * W_ + xc1;
        int b01 = yc1 * W_ + xc0, b11 = yc1 * W_ + xc1;
        float2 f00 = make_float2(__ldg(g1x + b00), __ldg(g1y + b00));
        float2 f10 = make_float2(__ldg(g1x + b10), __ldg(g1y + b10));
        float2 f01 = make_float2(__ldg(g1x + b01), __ldg(g1y + b01));
        float2 f11 = make_float2(__ldg(g1x + b11), __ldg(g1y + b11));
        return slow_eval(f00, f10, f01, f11, x0, y0, wx0, wx1, wy0, wy1, Gx, Gy);
    }
}

// Fast path: tile-relative coords (u,v > 0), packed f32x2 head/tail,
// lerp-form half2 bilerp.
__device__ __forceinline__ float dir_fast_u(const __half2* __restrict__ t1,
                                            u64 f2p, u64 uvb, u64 invp)
{
    u64 uvp; ADD_F32X2(uvp, uvb, f2p);
    float u, v; unpackf2(uvp, u, v);
    int iu = (int)u;                     // u,v > 0: trunc == floor
    int iv = (int)v;
    float wx1 = u - (float)iu;
    float wy1 = v - (float)iv;
    int b = iv * TW + iu;

    __half2 f00 = t1[b];
    __half2 f10 = t1[b + 1];
    __half2 f01 = t1[b + TW];
    __half2 f11 = t1[b + TW + 1];

    __half2 hx1 = __float2half2_rn(wx1);
    __half2 hy1 = __float2half2_rn(wy1);

    __half2 top = __hfma2(__hsub2(f10, f00), hx1, f00);
    __half2 bot = __hfma2(__hsub2(f11, f01), hx1, f01);
    __half2 r   = __hfma2(__hsub2(bot, top), hy1, top);
    float2 bf = __half22float2(r);

    u64 dp; ADD_F32X2(dp, f2p, packf2(bf.x, bf.y));
    MUL_F32X2(dp, dp, invp);
    float dx, dy; unpackf2(dp, dx, dy);
    return fast_sqrt(fmaf(dx, dx, fmaf(dy, dy, EPS2)));
}

__global__ __launch_bounds__(NT, 4)
void fused_cycle_kernel(const float* __restrict__ A, const float* __restrict__ B,
                        float* __restrict__ out)
{
    __shared__ __half2 tA[TSZ];
    __shared__ __half2 tB[TSZ];

    int n = blockIdx.z;
    const float* Ax = A + (size_t)n * 2 * HW_;
    const float* Ay = Ax + HW_;
    const float* Bx = B + (size_t)n * 2 * HW_;
    const float* By = Bx + HW_;

    int tx0 = blockIdx.x * BX - RX_;    // % 4 == 0 for interior bx
    int ty0 = blockIdx.y * RPB - RY_;
    int tid = threadIdx.y * BX + threadIdx.x;

    int dirty = 0;

    // Tile fill: tile cell == clamped-global value, quantized to half2.
    if (blockIdx.x >= 1 && blockIdx.x <= GX_ - 2) {
        __half2 macc = __float2half2_rn(0.0f);
        for (int i = tid; i < NV4; i += NT) {
            int ly = i / (TW / 4);
            int lxg = (i - ly * (TW / 4)) * 4;
            int gy = min(max(ty0 + ly, 0), H_ - 1);
            int idx = gy * W_ + tx0 + lxg;
            float4 ax = *(const float4*)(Ax + idx);
            float4 ay = *(const float4*)(Ay + idx);
            float4 bx = *(const float4*)(Bx + idx);
            float4 by = *(const float4*)(By + idx);
            int c = ly * TW + lxg;
            uint4 va = make_uint4(h2u(__floats2half2_rn(ax.x, ay.x)),
                                  h2u(__floats2half2_rn(ax.y, ay.y)),
                                  h2u(__floats2half2_rn(ax.z, ay.z)),
                                  h2u(__floats2half2_rn(ax.w, ay.w)));
            uint4 vb = make_uint4(h2u(__floats2half2_rn(bx.x, by.x)),
                                  h2u(__floats2half2_rn(bx.y, by.y)),
                                  h2u(__floats2half2_rn(bx.z, by.z)),
                                  h2u(__floats2half2_rn(bx.w, by.w)));
            *(uint4*)&tA[c] = va;
            *(uint4*)&tB[c] = vb;
            __half2 m0 = __hmax2(__habs2(u2h(va.x)), __habs2(u2h(va.y)));
            __half2 m1 = __hmax2(__habs2(u2h(va.z)), __habs2(u2h(va.w)));
            __half2 m2 = __hmax2(__habs2(u2h(vb.x)), __habs2(u2h(vb.y)));
            __half2 m3 = __hmax2(__habs2(u2h(vb.z)), __habs2(u2h(vb.w)));
            macc = __hmax2(macc, __hmax2(__hmax2(m0, m1), __hmax2(m2, m3)));
        }
        float hm = fmaxf(__half2float(__low2half(macc)),
                         __half2float(__high2half(macc)));
        if (hm >= CLEAN_TH_H) dirty = 1;
    } else {
        for (int i = tid; i < TSZ; i += NT) {
            int ly = i / TW, lx = i - ly * TW;
            int gx = min(max(tx0 + lx, 0), W_ - 1);
            int gy = min(max(ty0 + ly, 0), H_ - 1);
            int idx = gy * W_ + gx;
            float fax = __ldg(Ax + idx), fay = __ldg(Ay + idx);
            float fbx = __ldg(Bx + idx), fby = __ldg(By + idx);
            if (fmaxf(fmaxf(fabsf(fax), fabsf(fay)),
                      fmaxf(fabsf(fbx), fabsf(fby))) >= CLEAN_TH_F) dirty = 1;
            tA[i] = __floats2half2_rn(fax, fay);
            tB[i] = __floats2half2_rn(fbx, fby);
        }
    }

    bool dataClean = (__syncthreads_or(dirty) == 0);  // also the fill barrier

    bool blockInterior = (blockIdx.x >= 1) & (blockIdx.x <= GX_ - 2) &
                         (blockIdx.y >= 1) & (blockIdx.y <= GY_ - 2);

    float s = 0.0f;
    if (blockInterior & dataClean) {
        const u64 invp = packf2(INVW, INVH);
        float ub = (float)(threadIdx.x + RX_);
        int lown = (threadIdx.y + RY_) * TW + (threadIdx.x + RX_);

        // Hoisted own-loads: 8 conflict-free LDS.32 issued back-to-back.
        float2 ao[4], bo[4];
        #pragma unroll
        for (int r = 0; r < 4; r++) {
            ao[r] = __half22float2(tA[lown + r * BY * TW]);
            bo[r] = __half22float2(tB[lown + r * BY * TW]);
        }

        float vb = (float)(threadIdx.y + RY_);
        #pragma unroll
        for (int r = 0; r < 4; r++) {
            u64 uvb = packf2(ub, vb);
            s += dir_fast_u(tA, packf2(bo[r].x, bo[r].y), uvb, invp)
               + dir_fast_u(tB, packf2(ao[r].x, ao[r].y), uvb, invp);
            vb += (float)BY;
        }
    } else {
        int px = blockIdx.x * BX + threadIdx.x;
        int py0 = blockIdx.y * RPB + threadIdx.y;
        bool pxIn = ((unsigned)(px - 14) <= 737u);
        const u64 invp = packf2(INVW, INVH);
        float ub = (float)(px - tx0);
        #pragma unroll
        for (int r = 0; r < 4; r++) {
            int py = py0 + r * BY;
            bool fast = dataClean & pxIn & ((unsigned)(py - 14) <= 737u);
            if (fast) {
                int lrow = py - ty0;
                int lown = lrow * TW + (px - tx0);
                float2 bo = __half22float2(tB[lown]);
                float2 ao = __half22float2(tA[lown]);
                u64 uvb = packf2(ub, (float)lrow);
                s += dir_fast_u(tA, packf2(bo.x, bo.y), uvb, invp)
                   + dir_fast_u(tB, packf2(ao.x, ao.y), uvb, invp);
            } else {
                int idx = py * W_ + px;
                float aox = __ldg(Ax + idx), aoy = __ldg(Ay + idx);
                float box = __ldg(Bx + idx), boy = __ldg(By + idx);
                float Gx = (float)px * INVW;
                float Gy = (float)py * INVH;
                s += dir_diff(tA, Ax, Ay, box, boy, px, py, tx0, ty0, Gx, Gy)
                   + dir_diff(tB, Bx, By, aox, aoy, px, py, tx0, ty0, Gx, Gy);
            }
        }
    }

    // Block reduction (16 warps)
    #pragma unroll
    for (int o = 16; o > 0; o >>= 1)
        s += __shfl_down_sync(0xffffffffu, s, o);
    __shared__ float shred[NT / 32];
    if ((tid & 31) == 0) shred[tid >> 5] = s;
    __syncthreads();
    if (tid < 16) {
        float v = shred[tid];
        #pragma unroll
        for (int o = 8; o > 0; o >>= 1)
            v += __shfl_down_sync(0x0000ffffu, v, o);
        if (tid == 0) {
            int bid = blockIdx.x + GX_ * (blockIdx.y + GY_ * blockIdx.z);
            g_partials[bid] = v;
        }
    }

    // Last-block-standing fused final reduce (deterministic).
    __shared__ bool amLast;
    __threadfence();
    if (tid == 0) {
        unsigned long long old = atomicAdd(&g_ticket, 1ULL);
        amLast = ((old % (unsigned long long)NBLK) == (unsigned long long)(NBLK - 1));
    }
    __syncthreads();
    if (amLast) {
        const float4* p4 = (const float4*)g_partials;  // NBLK % 4 == 0
        const int n4 = NBLK / 4;                       // 1152
        double acc = 0.0;
        for (int i = tid; i < n4; i += NT) {
            float4 v = __ldcg(p4 + i);
            acc += (double)((v.x + v.y) + (v.z + v.w));
        }
        #pragma unroll
        for (int o = 16; o > 0; o >>= 1)
            acc += __shfl_down_sync(0xffffffffu, acc, o);
        __shared__ double shd[NT / 32];
        if ((tid & 31) == 0) shd[tid >> 5] = acc;
        __syncthreads();
        if (tid < 16) {
            double v = shd[tid];
            #pragma unroll
            for (int o = 8; o > 0; o >>= 1)
                v += __shfl_down_sync(0x0000ffffu, v, o);
            if (tid == 0)
                out[0] = (float)(v / ((double)N_ * (double)HW_));
        }
    }
}

extern "C" void kernel_launch(void* const* d_in, const int* in_sizes, int n_in,
                              void* d_out, int out_size)
{
    const float* A = (const float*)d_in[0];  // UV_AtoB
    const float* B = (const float*)d_in[1];  // UV_BtoA
    dim3 block(BX, BY);
    dim3 grid(GX_, GY_, N_);
    fused_cycle_kernel<<<grid, block>>>(A, B, (float*)d_out);
}